// round 2
// baseline (speedup 1.0000x reference)
#include <cuda_runtime.h>
#include <math.h>

#define LL 512
#define BB 128
#define DD 512
#define TT 200
#define EE 384
#define CC 128
#define HH 512
#define VV 46
#define G4H 2048

// ---------------- device scratch (static allocations only) ----------------
__device__ float g_keyf[BB * LL * CC];   // [b][l][c], bias folded in
__device__ float g_valf[BB * LL * CC];   // [b][l][c], bias folded in
__device__ float g_embW[VV * G4H];       // embedding @ w_ih0[:, :E]^T + b_ih0 + b_hh0
__device__ float g_bias1[G4H];
__device__ float g_bias2[G4H];
__device__ float g_h0T[2][HH * BB];      // transposed [k][b], double-buffered by t parity
__device__ float g_h1T[2][HH * BB];
__device__ float g_h2T[2][HH * BB];
__device__ float g_c0T[HH * BB];
__device__ float g_c1T[HH * BB];
__device__ float g_c2T[HH * BB];
__device__ float g_h2n[BB * HH];         // h2 in [b][k] layout for attention
__device__ float g_ctxT[CC * BB];        // context transposed [c][b]
__device__ float g_phiT[HH * CC];        // phi_w transposed [k][c]
__device__ int   g_tok[TT * BB];

__device__ __forceinline__ float sigmoidf_(float x) { return 1.f / (1.f + expf(-x)); }

// ---------------- precompute: keyf/valf  (GEMM: [L*B, D] x [D, 2C]) ----------------
// grid (1024, 4), block 256. tile 64 rows x 64 cols, BK=16, 4x4 per thread.
__global__ void __launch_bounds__(256) keyval_kernel(
    const float* __restrict__ lf,
    const float* __restrict__ key_w, const float* __restrict__ key_b,
    const float* __restrict__ value_w, const float* __restrict__ value_b)
{
    __shared__ __align__(16) float As[16][64];
    __shared__ __align__(16) float Bs[16][64];

    const int tid = threadIdx.x;
    const int m0 = blockIdx.x * 64;
    const int n0 = blockIdx.y * 64;
    const int ty = tid >> 4;      // 0..15
    const int tx = tid & 15;      // 0..15

    float acc[4][4];
#pragma unroll
    for (int i = 0; i < 4; i++)
#pragma unroll
        for (int j = 0; j < 4; j++) acc[i][j] = 0.f;

    const int mi = tid >> 2;          // 0..63
    const int kq = (tid & 3) * 4;     // 0,4,8,12

    for (int kb = 0; kb < DD; kb += 16) {
        // stage activations (64 rows x 16 k)
        {
            float4 v = *reinterpret_cast<const float4*>(&lf[(size_t)(m0 + mi) * DD + kb + kq]);
            As[kq + 0][mi] = v.x; As[kq + 1][mi] = v.y; As[kq + 2][mi] = v.z; As[kq + 3][mi] = v.w;
        }
        // stage weights (64 cols x 16 k)
        {
            int n = n0 + mi;
            const float* wrow = (n < CC) ? (key_w + (size_t)n * DD) : (value_w + (size_t)(n - CC) * DD);
            float4 v = *reinterpret_cast<const float4*>(&wrow[kb + kq]);
            Bs[kq + 0][mi] = v.x; Bs[kq + 1][mi] = v.y; Bs[kq + 2][mi] = v.z; Bs[kq + 3][mi] = v.w;
        }
        __syncthreads();
#pragma unroll
        for (int k = 0; k < 16; k++) {
            float4 av = *reinterpret_cast<const float4*>(&As[k][ty * 4]);
            float4 bv = *reinterpret_cast<const float4*>(&Bs[k][tx * 4]);
            float a[4] = {av.x, av.y, av.z, av.w};
            float b[4] = {bv.x, bv.y, bv.z, bv.w};
#pragma unroll
            for (int i = 0; i < 4; i++)
#pragma unroll
                for (int j = 0; j < 4; j++) acc[i][j] = fmaf(a[i], b[j], acc[i][j]);
        }
        __syncthreads();
    }

#pragma unroll
    for (int i = 0; i < 4; i++) {
        int m = m0 + ty * 4 + i;
        int l = m >> 7, b = m & 127;
#pragma unroll
        for (int j = 0; j < 4; j++) {
            int n = n0 + tx * 4 + j;
            if (n < CC)
                g_keyf[((size_t)b << 16) + l * CC + n] = acc[i][j] + key_b[n];
            else
                g_valf[((size_t)b << 16) + l * CC + (n - CC)] = acc[i][j] + value_b[n - CC];
        }
    }
}

// ---------------- precompute: embW ----------------
__global__ void __launch_bounds__(256) embw_kernel(
    const float* __restrict__ emb, const float* __restrict__ w_ih0,
    const float* __restrict__ b_ih0, const float* __restrict__ b_hh0)
{
    __shared__ float es[EE];
    const int v = blockIdx.x, tid = threadIdx.x;
    for (int i = tid; i < EE; i += 256) es[i] = emb[(size_t)v * EE + i];
    __syncthreads();
    for (int j = tid; j < G4H; j += 256) {
        const float* wr = w_ih0 + (size_t)j * (EE + CC);
        float a0 = b_ih0[j] + b_hh0[j], a1 = 0.f, a2 = 0.f, a3 = 0.f;
        for (int e = 0; e < EE; e += 4) {
            a0 = fmaf(es[e + 0], wr[e + 0], a0);
            a1 = fmaf(es[e + 1], wr[e + 1], a1);
            a2 = fmaf(es[e + 2], wr[e + 2], a2);
            a3 = fmaf(es[e + 3], wr[e + 3], a3);
        }
        g_embW[(size_t)v * G4H + j] = a0 + a1 + a2 + a3;
    }
}

// ---------------- precompute misc ----------------
__global__ void bias_kernel(const float* __restrict__ bi1, const float* __restrict__ bh1,
                            const float* __restrict__ bi2, const float* __restrict__ bh2)
{
    int i = blockIdx.x * blockDim.x + threadIdx.x;
    if (i < G4H) { g_bias1[i] = bi1[i] + bh1[i]; g_bias2[i] = bi2[i] + bh2[i]; }
}

__global__ void phit_kernel(const float* __restrict__ phi_w)
{
    int i = blockIdx.x * blockDim.x + threadIdx.x;
    if (i < HH * CC) {
        int k = i >> 7, c = i & 127;
        g_phiT[i] = phi_w[(size_t)c * HH + k];
    }
}

__global__ void tok_kernel(const int* __restrict__ transcript)
{
    int i = blockIdx.x * blockDim.x + threadIdx.x;
    if (i < TT * BB) {
        int t = i / BB, b = i % BB;
        g_tok[i] = (t == 0) ? 0 : transcript[(size_t)(t - 1) * BB + b];
    }
}

__global__ void init_kernel(const float* __restrict__ hx0, const float* __restrict__ cx0,
                            const float* __restrict__ hx1, const float* __restrict__ cx1,
                            const float* __restrict__ hx2, const float* __restrict__ cx2)
{
    int i = blockIdx.x * blockDim.x + threadIdx.x;
    if (i < HH * BB) {
        int k = i >> 7, b = i & 127;
        g_h0T[0][i] = hx0[k]; g_c0T[i] = cx0[k];
        g_h1T[0][i] = hx1[k]; g_c1T[i] = cx1[k];
        g_h2T[0][i] = hx2[k]; g_c2T[i] = cx2[k];
        g_h2n[(size_t)b * HH + k] = hx2[k];
    }
}

// ---------------- LSTM layer: gates GEMM + nonlinearity ----------------
// grid 128 (4 hidden units per block), block 256. Computes 128B x 16cols (4 gates x 4 hh).
__global__ void __launch_bounds__(256) lstm_kernel(int layer, int t,
    const float* __restrict__ w_ih, const float* __restrict__ w_hh)
{
    __shared__ __align__(16) float Xs[32 * 128];
    __shared__ float Ws[16 * 33];
    __shared__ float Gs[16 * 128];

    const int tid = threadIdx.x;
    const int hhbase = blockIdx.x * 4;
    const int tx = tid & 7;        // 0..7 -> 2 cols
    const int ty = tid >> 3;       // 0..31 -> 4 batches
    const int b0 = ty * 4;
    const int cc0 = tx * 2, cc1 = tx * 2 + 1;
    const int jr0 = ((cc0 >> 2) << 9) + hhbase + (cc0 & 3);
    const int jr1 = ((cc1 >> 2) << 9) + hhbase + (cc1 & 3);

    const int p = t & 1;
    const float* xaT; int KA; const float* wa; const float* hT;
    float* hoT; float* coT; const float* pre; const int* tok = nullptr; float* hN = nullptr;
    if (layer == 0) {
        xaT = g_ctxT; KA = CC; wa = w_ih + EE;
        hT = g_h0T[p]; hoT = g_h0T[p ^ 1]; coT = g_c0T;
        pre = g_embW; tok = g_tok + (size_t)t * BB;
    } else if (layer == 1) {
        xaT = g_h0T[p ^ 1]; KA = HH; wa = w_ih;
        hT = g_h1T[p]; hoT = g_h1T[p ^ 1]; coT = g_c1T;
        pre = g_bias1;
    } else {
        xaT = g_h1T[p ^ 1]; KA = HH; wa = w_ih;
        hT = g_h2T[p]; hoT = g_h2T[p ^ 1]; coT = g_c2T;
        pre = g_bias2; hN = g_h2n;
    }

    float a00, a01, a02, a03, a10, a11, a12, a13;
    if (layer == 0) {
        int t0 = tok[b0], t1 = tok[b0 + 1], t2 = tok[b0 + 2], t3 = tok[b0 + 3];
        a00 = pre[(size_t)t0 * G4H + jr0]; a01 = pre[(size_t)t1 * G4H + jr0];
        a02 = pre[(size_t)t2 * G4H + jr0]; a03 = pre[(size_t)t3 * G4H + jr0];
        a10 = pre[(size_t)t0 * G4H + jr1]; a11 = pre[(size_t)t1 * G4H + jr1];
        a12 = pre[(size_t)t2 * G4H + jr1]; a13 = pre[(size_t)t3 * G4H + jr1];
    } else {
        float p0 = pre[jr0], p1 = pre[jr1];
        a00 = a01 = a02 = a03 = p0;
        a10 = a11 = a12 = a13 = p1;
    }

    for (int phase = 0; phase < 2; phase++) {
        const float* xT = phase ? hT : xaT;
        const float* w  = phase ? w_hh : wa;
        const int K = phase ? HH : KA;
        for (int kb = 0; kb < K; kb += 32) {
            // stage activations [32k x 128b]
#pragma unroll
            for (int i = 0; i < 16; i++) {
                int s = tid + i * 256;
                int k = s >> 7, bb = s & 127;
                Xs[(k << 7) + bb] = xT[(size_t)(kb + k) * BB + bb];
            }
            // stage weights [16cc x 32k]
#pragma unroll
            for (int i = 0; i < 2; i++) {
                int s = tid + i * 256;
                int cc = s >> 5, k = s & 31;
                int jrow = ((cc >> 2) << 9) + hhbase + (cc & 3);
                Ws[cc * 33 + k] = w[(size_t)jrow * 512 + kb + k];
            }
            __syncthreads();
#pragma unroll
            for (int k = 0; k < 32; k++) {
                const float4 xv = *reinterpret_cast<const float4*>(&Xs[(k << 7) + b0]);
                const float w0 = Ws[cc0 * 33 + k];
                const float w1 = Ws[cc1 * 33 + k];
                a00 = fmaf(xv.x, w0, a00); a01 = fmaf(xv.y, w0, a01);
                a02 = fmaf(xv.z, w0, a02); a03 = fmaf(xv.w, w0, a03);
                a10 = fmaf(xv.x, w1, a10); a11 = fmaf(xv.y, w1, a11);
                a12 = fmaf(xv.z, w1, a12); a13 = fmaf(xv.w, w1, a13);
            }
            __syncthreads();
        }
    }

    // stage gates and apply LSTM cell
    Gs[cc0 * 128 + b0 + 0] = a00; Gs[cc0 * 128 + b0 + 1] = a01;
    Gs[cc0 * 128 + b0 + 2] = a02; Gs[cc0 * 128 + b0 + 3] = a03;
    Gs[cc1 * 128 + b0 + 0] = a10; Gs[cc1 * 128 + b0 + 1] = a11;
    Gs[cc1 * 128 + b0 + 2] = a12; Gs[cc1 * 128 + b0 + 3] = a13;
    __syncthreads();

#pragma unroll
    for (int cell = tid; cell < 512; cell += 256) {
        int hh = cell >> 7, b = cell & 127;
        float gi = Gs[(0  + hh) * 128 + b];
        float gf = Gs[(4  + hh) * 128 + b];
        float gg = Gs[(8  + hh) * 128 + b];
        float go = Gs[(12 + hh) * 128 + b];
        int hidx = hhbase + hh;
        float c = sigmoidf_(gf) * coT[hidx * BB + b] + sigmoidf_(gi) * tanhf(gg);
        float h = sigmoidf_(go) * tanhf(c);
        coT[hidx * BB + b] = c;
        hoT[hidx * BB + b] = h;
        if (hN) hN[(size_t)b * HH + hidx] = h;
    }
}

// ---------------- attention + output projection (one block per batch row) ----------------
__global__ void __launch_bounds__(256) attn_kernel(
    const int* __restrict__ lens,
    const float* __restrict__ phi_b,
    const float* __restrict__ out_w, const float* __restrict__ out_b,
    float* __restrict__ attn_out,     // may be null; pre-offset by t*B*L
    float* __restrict__ logits_out)   // may be null; pre-offset by t*B*V
{
    __shared__ __align__(16) float h2s[HH];
    __shared__ __align__(16) float qs[CC];
    __shared__ __align__(16) float as[LL];
    __shared__ float ctxsm[CC];
    __shared__ float red[256];

    const int b = blockIdx.x, tid = threadIdx.x;

    h2s[tid]       = g_h2n[(size_t)b * HH + tid];
    h2s[tid + 256] = g_h2n[(size_t)b * HH + tid + 256];
    __syncthreads();

    // q = h2 @ phi_w^T + phi_b
    if (tid < CC) {
        float a0 = 0.f, a1 = 0.f, a2 = 0.f, a3 = 0.f;
        for (int k = 0; k < HH; k += 4) {
            a0 = fmaf(h2s[k + 0], g_phiT[(k + 0) * CC + tid], a0);
            a1 = fmaf(h2s[k + 1], g_phiT[(k + 1) * CC + tid], a1);
            a2 = fmaf(h2s[k + 2], g_phiT[(k + 2) * CC + tid], a2);
            a3 = fmaf(h2s[k + 3], g_phiT[(k + 3) * CC + tid], a3);
        }
        qs[tid] = a0 + a1 + a2 + a3 + phi_b[tid];
    }
    __syncthreads();

    // energies (2 l per thread)
    float e[2];
#pragma unroll
    for (int j = 0; j < 2; j++) {
        int l = tid + j * 256;
        const float4* kp = reinterpret_cast<const float4*>(g_keyf + ((size_t)b << 16) + (size_t)l * CC);
        const float4* qp = reinterpret_cast<const float4*>(qs);
        float a0 = 0.f, a1 = 0.f, a2 = 0.f, a3 = 0.f;
#pragma unroll 8
        for (int c = 0; c < 32; c++) {
            float4 kv = kp[c], qv = qp[c];
            a0 = fmaf(kv.x, qv.x, a0); a1 = fmaf(kv.y, qv.y, a1);
            a2 = fmaf(kv.z, qv.z, a2); a3 = fmaf(kv.w, qv.w, a3);
        }
        e[j] = a0 + a1 + a2 + a3;
    }

    // max reduce (over all L; masked softmax normalization cancels the difference)
    red[tid] = fmaxf(e[0], e[1]);
    __syncthreads();
    for (int s = 128; s > 0; s >>= 1) {
        if (tid < s) red[tid] = fmaxf(red[tid], red[tid + s]);
        __syncthreads();
    }
    const float mx = red[0];
    __syncthreads();

    const int len = lens[b];
    float p0 = (tid < len)       ? expf(e[0] - mx) : 0.f;
    float p1 = (tid + 256 < len) ? expf(e[1] - mx) : 0.f;
    red[tid] = p0 + p1;
    __syncthreads();
    for (int s = 128; s > 0; s >>= 1) {
        if (tid < s) red[tid] += red[tid + s];
        __syncthreads();
    }
    const float inv = 1.f / fmaxf(red[0], 1e-12f);
    __syncthreads();

    float av0 = p0 * inv, av1 = p1 * inv;
    as[tid] = av0; as[tid + 256] = av1;
    if (attn_out) {
        attn_out[(size_t)b * LL + tid]       = av0;
        attn_out[(size_t)b * LL + tid + 256] = av1;
    }
    __syncthreads();

    // ctx = a @ valf
    if (tid < CC) {
        const float* vp = g_valf + ((size_t)b << 16) + tid;
        float a0 = 0.f, a1 = 0.f, a2 = 0.f, a3 = 0.f;
        for (int l = 0; l < LL; l += 4) {
            a0 = fmaf(as[l + 0], vp[(l + 0) * CC], a0);
            a1 = fmaf(as[l + 1], vp[(l + 1) * CC], a1);
            a2 = fmaf(as[l + 2], vp[(l + 2) * CC], a2);
            a3 = fmaf(as[l + 3], vp[(l + 3) * CC], a3);
        }
        float ctxv = a0 + a1 + a2 + a3;
        ctxsm[tid] = ctxv;
        g_ctxT[tid * BB + b] = ctxv;
    }
    __syncthreads();

    // logits = [h2, ctx] @ out_w^T + out_b
    if (logits_out && tid < VV) {
        const float* wr = out_w + (size_t)tid * (HH + CC);
        float a0 = out_b[tid], a1 = 0.f, a2 = 0.f, a3 = 0.f;
        for (int k = 0; k < HH; k += 4) {
            a0 = fmaf(h2s[k + 0], wr[k + 0], a0);
            a1 = fmaf(h2s[k + 1], wr[k + 1], a1);
            a2 = fmaf(h2s[k + 2], wr[k + 2], a2);
            a3 = fmaf(h2s[k + 3], wr[k + 3], a3);
        }
        for (int k = 0; k < CC; k += 4) {
            a0 = fmaf(ctxsm[k + 0], wr[HH + k + 0], a0);
            a1 = fmaf(ctxsm[k + 1], wr[HH + k + 1], a1);
            a2 = fmaf(ctxsm[k + 2], wr[HH + k + 2], a2);
            a3 = fmaf(ctxsm[k + 3], wr[HH + k + 3], a3);
        }
        logits_out[(size_t)b * VV + tid] = a0 + a1 + a2 + a3;
    }
}

// ---------------- launch ----------------
extern "C" void kernel_launch(void* const* d_in, const int* in_sizes, int n_in,
                              void* d_out, int out_size)
{
    const float* lf         = (const float*)d_in[0];
    const int*   lens       = (const int*)  d_in[1];
    const int*   transcript = (const int*)  d_in[2];
    const float* emb        = (const float*)d_in[3];
    const float* w_ih0 = (const float*)d_in[4];
    const float* w_hh0 = (const float*)d_in[5];
    const float* b_ih0 = (const float*)d_in[6];
    const float* b_hh0 = (const float*)d_in[7];
    const float* w_ih1 = (const float*)d_in[8];
    const float* w_hh1 = (const float*)d_in[9];
    const float* b_ih1 = (const float*)d_in[10];
    const float* b_hh1 = (const float*)d_in[11];
    const float* w_ih2 = (const float*)d_in[12];
    const float* w_hh2 = (const float*)d_in[13];
    const float* b_ih2 = (const float*)d_in[14];
    const float* b_hh2 = (const float*)d_in[15];
    const float* phi_w = (const float*)d_in[16];
    const float* phi_b = (const float*)d_in[17];
    const float* key_w = (const float*)d_in[18];
    const float* key_b = (const float*)d_in[19];
    const float* value_w = (const float*)d_in[20];
    const float* value_b = (const float*)d_in[21];
    const float* out_w = (const float*)d_in[22];
    const float* out_b = (const float*)d_in[23];
    const float* hx0 = (const float*)d_in[24];
    const float* cx0 = (const float*)d_in[25];
    const float* hx1 = (const float*)d_in[26];
    const float* cx1 = (const float*)d_in[27];
    const float* hx2 = (const float*)d_in[28];
    const float* cx2 = (const float*)d_in[29];

    float* out = (float*)d_out;
    float* logits_base = out;                               // [T,B,V]
    float* attn_base   = out + (size_t)TT * BB * VV;        // [T,B,L]

    keyval_kernel<<<dim3(1024, 4), 256>>>(lf, key_w, key_b, value_w, value_b);
    embw_kernel<<<VV, 256>>>(emb, w_ih0, b_ih0, b_hh0);
    bias_kernel<<<8, 256>>>(b_ih1, b_hh1, b_ih2, b_hh2);
    phit_kernel<<<256, 256>>>(phi_w);
    tok_kernel<<<(TT * BB + 255) / 256, 256>>>(transcript);
    init_kernel<<<256, 256>>>(hx0, cx0, hx1, cx1, hx2, cx2);

    // initial context from initial decoder state (no outputs written)
    attn_kernel<<<BB, 256>>>(lens, phi_b, out_w, out_b, nullptr, nullptr);

    for (int t = 0; t < TT; t++) {
        lstm_kernel<<<128, 256>>>(0, t, w_ih0, w_hh0);
        lstm_kernel<<<128, 256>>>(1, t, w_ih1, w_hh1);
        lstm_kernel<<<128, 256>>>(2, t, w_ih2, w_hh2);
        attn_kernel<<<BB, 256>>>(lens, phi_b, out_w, out_b,
                                 attn_base + (size_t)t * BB * LL,
                                 logits_base + (size_t)t * BB * VV);
    }
}

// round 3
// speedup vs baseline: 1.9050x; 1.9050x over previous
#include <cuda_runtime.h>
#include <math.h>

#define LL 512
#define BB 128
#define DD 512
#define TT 200
#define EE 384
#define CC 128
#define HH 512
#define VV 46
#define G4H 2048
#define NBLK 128

typedef unsigned long long ull;

// ---------------- device scratch ----------------
__device__ __align__(128) float g_keyfT[BB * CC * LL];  // [b][c][l]
__device__ __align__(128) float g_valf[BB * LL * CC];   // [b][l][c]
__device__ __align__(128) float g_embW[VV * G4H];
__device__ __align__(128) float g_bias1[G4H];
__device__ __align__(128) float g_bias2[G4H];
__device__ __align__(128) float g_h0T[2][HH * BB];
__device__ __align__(128) float g_h1T[2][HH * BB];
__device__ __align__(128) float g_h2T[2][HH * BB];
__device__ __align__(128) float g_c0T[HH * BB];
__device__ __align__(128) float g_c1T[HH * BB];
__device__ __align__(128) float g_c2T[HH * BB];
__device__ __align__(128) float g_h2n[BB * HH];
__device__ __align__(128) float g_ctxT[CC * BB];
__device__ __align__(128) float g_phiT[HH * CC];        // [k][c]
__device__ int   g_tok[TT * BB];
__device__ unsigned g_barctr;

__device__ __forceinline__ float sigmoidf_(float x) { return 1.f / (1.f + expf(-x)); }

__device__ __forceinline__ ull pack2(float lo, float hi) {
    ull r; asm("mov.b64 %0, {%1, %2};" : "=l"(r) : "f"(lo), "f"(hi)); return r;
}
__device__ __forceinline__ float2 unpack2(ull v) {
    float2 r; asm("mov.b64 {%0, %1}, %2;" : "=f"(r.x), "=f"(r.y) : "l"(v)); return r;
}
__device__ __forceinline__ void fma2(ull& d, ull a, ull b) {
    asm("fma.rn.f32x2 %0, %1, %2, %0;" : "+l"(d) : "l"(a), "l"(b));
}

// ---------------- shared memory layout ----------------
struct SUg { float Xs[2][32 * 128]; float Ws[2][16 * 36]; };
struct SUa {
    float h2s[512]; float qs[128]; float qp[1024];
    float as[512];  float ctxp[1024]; float ctxs[128]; float red[256];
};
union SU { SUg g; SUa a; };

// ---------------- grid barrier ----------------
__device__ __forceinline__ void gbar(unsigned& tgt) {
    __threadfence();
    __syncthreads();
    if (threadIdx.x == 0) {
        atomicAdd(&g_barctr, 1u);
        unsigned v;
        do {
            asm volatile("ld.acquire.gpu.u32 %0, [%1];" : "=r"(v) : "l"(&g_barctr) : "memory");
        } while (v < tgt);
    }
    __syncthreads();
    tgt += NBLK;
}

// ---------------- cp.async helpers ----------------
__device__ __forceinline__ void cp_cg16(float* dst, const float* src) {
    unsigned d = (unsigned)__cvta_generic_to_shared(dst);
    asm volatile("cp.async.cg.shared.global [%0], [%1], 16;" :: "r"(d), "l"(src) : "memory");
}
__device__ __forceinline__ void cp_ca16(float* dst, const float* src) {
    unsigned d = (unsigned)__cvta_generic_to_shared(dst);
    asm volatile("cp.async.ca.shared.global [%0], [%1], 16;" :: "r"(d), "l"(src) : "memory");
}

__device__ __forceinline__ void issue_chunk(SU* su, int buf, int c, int nc0, int hhbase,
    const float* xaT, const float* wa, int wstride, const float* hT, const float* whh)
{
    const int tid = threadIdx.x;
    const float* xs; const float* w; int kb, ws;
    if (c < nc0) { xs = xaT; w = wa; ws = wstride; kb = c * 32; }
    else         { xs = hT;  w = whh; ws = 512;    kb = (c - nc0) * 32; }
    float* Xb = su->g.Xs[buf];
    float* Wb = su->g.Ws[buf];
#pragma unroll
    for (int i = 0; i < 4; i++) {
        int idx4 = tid + i * 256;
        const float* src = xs + ((size_t)(kb + (idx4 >> 5)) << 7) + ((idx4 & 31) << 2);
        cp_cg16(Xb + (idx4 << 2), src);
    }
    if (tid < 128) {
        int cc = tid >> 3, kq = (tid & 7) << 2;
        int jrow = ((cc >> 2) << 9) + hhbase + (cc & 3);
        cp_ca16(Wb + cc * 36 + kq, w + (size_t)jrow * ws + kb + kq);
    }
    asm volatile("cp.async.commit_group;" ::: "memory");
}

// ---------------- LSTM phase ----------------
__device__ void lstm_phase(SU* su, float* Gs, int hhbase,
    const float* xaT, int nc0, const float* wa, int wstride,
    const float* hT, const float* whh,
    const float* pre, const int* tokp,
    float* hoT, float* coT, float* hN)
{
    const int tid = threadIdx.x;
    const int tx = tid & 7, ty = tid >> 3;
    const int b0 = ty * 4;
    const int cc0 = tx * 2, cc1 = cc0 + 1;
    const int jr0 = ((cc0 >> 2) << 9) + hhbase + (cc0 & 3);
    const int jr1 = ((cc1 >> 2) << 9) + hhbase + (cc1 & 3);

    ull acc0, acc1, acc2, acc3;
    if (tokp) {
        int t0 = tokp[b0], t1 = tokp[b0 + 1], t2 = tokp[b0 + 2], t3 = tokp[b0 + 3];
        acc0 = pack2(pre[(size_t)t0 * G4H + jr0], pre[(size_t)t1 * G4H + jr0]);
        acc1 = pack2(pre[(size_t)t2 * G4H + jr0], pre[(size_t)t3 * G4H + jr0]);
        acc2 = pack2(pre[(size_t)t0 * G4H + jr1], pre[(size_t)t1 * G4H + jr1]);
        acc3 = pack2(pre[(size_t)t2 * G4H + jr1], pre[(size_t)t3 * G4H + jr1]);
    } else {
        float p0 = pre[jr0], p1 = pre[jr1];
        acc0 = acc1 = pack2(p0, p0);
        acc2 = acc3 = pack2(p1, p1);
    }

    const int total = nc0 + 16;
    issue_chunk(su, 0, 0, nc0, hhbase, xaT, wa, wstride, hT, whh);
    int buf = 0;
    for (int c = 0; c < total; c++) {
        if (c + 1 < total) {
            issue_chunk(su, buf ^ 1, c + 1, nc0, hhbase, xaT, wa, wstride, hT, whh);
            asm volatile("cp.async.wait_group 1;" ::: "memory");
        } else {
            asm volatile("cp.async.wait_group 0;" ::: "memory");
        }
        __syncthreads();
        const float* Xs = su->g.Xs[buf];
        const float* Ws = su->g.Ws[buf];
#pragma unroll
        for (int k = 0; k < 32; k += 2) {
            ulonglong2 x0 = *reinterpret_cast<const ulonglong2*>(&Xs[((k) << 7) + b0]);
            ulonglong2 x1 = *reinterpret_cast<const ulonglong2*>(&Xs[((k + 1) << 7) + b0]);
            float2 wp0 = *reinterpret_cast<const float2*>(&Ws[cc0 * 36 + k]);
            float2 wp1 = *reinterpret_cast<const float2*>(&Ws[cc1 * 36 + k]);
            ull w00 = pack2(wp0.x, wp0.x), w01 = pack2(wp0.y, wp0.y);
            ull w10 = pack2(wp1.x, wp1.x), w11 = pack2(wp1.y, wp1.y);
            fma2(acc0, x0.x, w00); fma2(acc1, x0.y, w00);
            fma2(acc2, x0.x, w10); fma2(acc3, x0.y, w10);
            fma2(acc0, x1.x, w01); fma2(acc1, x1.y, w01);
            fma2(acc2, x1.x, w11); fma2(acc3, x1.y, w11);
        }
        __syncthreads();
        buf ^= 1;
    }

    float2 v;
    v = unpack2(acc0); *reinterpret_cast<float2*>(&Gs[cc0 * 128 + b0])     = v;
    v = unpack2(acc1); *reinterpret_cast<float2*>(&Gs[cc0 * 128 + b0 + 2]) = v;
    v = unpack2(acc2); *reinterpret_cast<float2*>(&Gs[cc1 * 128 + b0])     = v;
    v = unpack2(acc3); *reinterpret_cast<float2*>(&Gs[cc1 * 128 + b0 + 2]) = v;
    __syncthreads();

#pragma unroll
    for (int cell = tid; cell < 512; cell += 256) {
        int hh = cell >> 7, b = cell & 127;
        float gi = Gs[(0  + hh) * 128 + b];
        float gf = Gs[(4  + hh) * 128 + b];
        float gg = Gs[(8  + hh) * 128 + b];
        float go = Gs[(12 + hh) * 128 + b];
        int hidx = hhbase + hh;
        float cst = sigmoidf_(gf) * coT[hidx * 128 + b] + sigmoidf_(gi) * tanhf(gg);
        float h = sigmoidf_(go) * tanhf(cst);
        coT[hidx * 128 + b] = cst;
        hoT[hidx * 128 + b] = h;
        if (hN) hN[(size_t)b * 512 + hidx] = h;
    }
}

// ---------------- attention phase (block = batch) ----------------
__device__ void attn_phase(SU* su, int b, const int* lens, const float* phi_b,
    const float* out_w, const float* out_b,
    float* attn_out, float* logits_out)
{
    const int tid = threadIdx.x;
    const int warp = tid >> 5, lane = tid & 31;
    SUa* a = &su->a;

    a->h2s[tid]       = __ldcg(&g_h2n[(size_t)b * 512 + tid]);
    a->h2s[tid + 256] = __ldcg(&g_h2n[(size_t)b * 512 + tid + 256]);
    __syncthreads();

    // q partials: warp w handles k-slice [w*64, w*64+64)
    {
        float4 acc = make_float4(0.f, 0.f, 0.f, 0.f);
        for (int kk = 0; kk < 64; kk++) {
            int k = warp * 64 + kk;
            float hv = a->h2s[k];
            float4 pv = *reinterpret_cast<const float4*>(&g_phiT[(k << 7) + lane * 4]);
            acc.x = fmaf(hv, pv.x, acc.x); acc.y = fmaf(hv, pv.y, acc.y);
            acc.z = fmaf(hv, pv.z, acc.z); acc.w = fmaf(hv, pv.w, acc.w);
        }
        *reinterpret_cast<float4*>(&a->qp[warp * 128 + lane * 4]) = acc;
    }
    __syncthreads();
    if (tid < 128) {
        float q = phi_b[tid];
#pragma unroll
        for (int w = 0; w < 8; w++) q += a->qp[w * 128 + tid];
        a->qs[tid] = q;
    }
    __syncthreads();

    // energies: thread (half, tl) -> 4 l's over half the c-range
    {
        int half = tid >> 7, tl = tid & 127, l0 = tl * 4;
        float e0 = 0.f, e1 = 0.f, e2 = 0.f, e3 = 0.f;
        const float* kf = g_keyfT + ((size_t)b << 16) + l0;
        int c0 = half * 64;
#pragma unroll 4
        for (int c = c0; c < c0 + 64; c++) {
            float4 kv = __ldcg(reinterpret_cast<const float4*>(kf + ((size_t)c << 9)));
            float q = a->qs[c];
            e0 = fmaf(kv.x, q, e0); e1 = fmaf(kv.y, q, e1);
            e2 = fmaf(kv.z, q, e2); e3 = fmaf(kv.w, q, e3);
        }
        __syncthreads();  // qp reuse
        *reinterpret_cast<float4*>(&a->qp[half * 512 + l0]) = make_float4(e0, e1, e2, e3);
    }
    __syncthreads();

    float e0 = a->qp[tid]       + a->qp[512 + tid];
    float e1 = a->qp[tid + 256] + a->qp[512 + tid + 256];

    // softmax (max over all L; mask+renorm == masked softmax)
    a->red[tid] = fmaxf(e0, e1);
    __syncthreads();
    for (int s = 128; s > 0; s >>= 1) {
        if (tid < s) a->red[tid] = fmaxf(a->red[tid], a->red[tid + s]);
        __syncthreads();
    }
    const float mx = a->red[0];
    __syncthreads();

    const int len = lens[b];
    float p0 = (tid < len)       ? expf(e0 - mx) : 0.f;
    float p1 = (tid + 256 < len) ? expf(e1 - mx) : 0.f;
    a->red[tid] = p0 + p1;
    __syncthreads();
    for (int s = 128; s > 0; s >>= 1) {
        if (tid < s) a->red[tid] += a->red[tid + s];
        __syncthreads();
    }
    const float inv = 1.f / fmaxf(a->red[0], 1e-12f);
    __syncthreads();

    float av0 = p0 * inv, av1 = p1 * inv;
    a->as[tid] = av0; a->as[tid + 256] = av1;
    if (attn_out) {
        attn_out[(size_t)b * LL + tid]       = av0;
        attn_out[(size_t)b * LL + tid + 256] = av1;
    }
    __syncthreads();

    // ctx partials: warp w handles l-slice [w*64, w*64+64)
    {
        float c0v = 0.f, c1v = 0.f, c2v = 0.f, c3v = 0.f;
        const float* vf = g_valf + ((size_t)b << 16) + lane * 4;
        for (int i = 0; i < 64; i++) {
            int l = warp * 64 + i;
            float4 vv = __ldcg(reinterpret_cast<const float4*>(vf + ((size_t)l << 7)));
            float av = a->as[l];
            c0v = fmaf(vv.x, av, c0v); c1v = fmaf(vv.y, av, c1v);
            c2v = fmaf(vv.z, av, c2v); c3v = fmaf(vv.w, av, c3v);
        }
        *reinterpret_cast<float4*>(&a->ctxp[warp * 128 + lane * 4]) = make_float4(c0v, c1v, c2v, c3v);
    }
    __syncthreads();
    if (tid < 128) {
        float c = 0.f;
#pragma unroll
        for (int w = 0; w < 8; w++) c += a->ctxp[w * 128 + tid];
        a->ctxs[tid] = c;
        g_ctxT[tid * 128 + b] = c;
    }
    __syncthreads();

    // logits: warp w handles v = w, w+8, ...
    if (logits_out) {
        for (int v = warp; v < VV; v += 8) {
            const float* wr = out_w + (size_t)v * (HH + CC);
            float acc = 0.f;
#pragma unroll
            for (int it = 0; it < 5; it++) {
                int k0 = it * 128 + lane * 4;
                float4 wv = *reinterpret_cast<const float4*>(&wr[k0]);
                float4 xv = (it < 4) ? *reinterpret_cast<const float4*>(&a->h2s[k0])
                                     : *reinterpret_cast<const float4*>(&a->ctxs[k0 - 512]);
                acc = fmaf(wv.x, xv.x, acc); acc = fmaf(wv.y, xv.y, acc);
                acc = fmaf(wv.z, xv.z, acc); acc = fmaf(wv.w, xv.w, acc);
            }
#pragma unroll
            for (int off = 16; off > 0; off >>= 1)
                acc += __shfl_xor_sync(0xFFFFFFFF, acc, off);
            if (lane == 0) logits_out[(size_t)b * VV + v] = acc + out_b[v];
        }
    }
}

// ---------------- persistent kernel ----------------
__global__ void __launch_bounds__(256, 1) speller_persistent(
    const float* __restrict__ wih0, const float* __restrict__ whh0,
    const float* __restrict__ wih1, const float* __restrict__ whh1,
    const float* __restrict__ wih2, const float* __restrict__ whh2,
    const int* __restrict__ lens, const float* __restrict__ phi_b,
    const float* __restrict__ out_w, const float* __restrict__ out_b,
    float* __restrict__ attn_base, float* __restrict__ logits_base)
{
    __shared__ SU su;
    __shared__ float Gs[2048];
    const int bk = blockIdx.x;
    const int hhbase = bk * 4;
    unsigned tgt = NBLK;

    // initial context from initial decoder state
    attn_phase(&su, bk, lens, phi_b, out_w, out_b, nullptr, nullptr);
    gbar(tgt);

    for (int t = 0; t < TT; t++) {
        const int p = t & 1;
        lstm_phase(&su, Gs, hhbase,
                   g_ctxT, 4, wih0 + EE, EE + CC,
                   g_h0T[p], whh0,
                   g_embW, g_tok + (size_t)t * BB,
                   g_h0T[p ^ 1], g_c0T, nullptr);
        gbar(tgt);
        lstm_phase(&su, Gs, hhbase,
                   g_h0T[p ^ 1], 16, wih1, 512,
                   g_h1T[p], whh1,
                   g_bias1, nullptr,
                   g_h1T[p ^ 1], g_c1T, nullptr);
        gbar(tgt);
        lstm_phase(&su, Gs, hhbase,
                   g_h1T[p ^ 1], 16, wih2, 512,
                   g_h2T[p], whh2,
                   g_bias2, nullptr,
                   g_h2T[p ^ 1], g_c2T, g_h2n);
        gbar(tgt);
        attn_phase(&su, bk, lens, phi_b, out_w, out_b,
                   attn_base + (size_t)t * BB * LL,
                   logits_base + (size_t)t * BB * VV);
        gbar(tgt);
    }
}

// ---------------- precompute: keyf(T)/valf ----------------
__global__ void __launch_bounds__(256) keyval_kernel(
    const float* __restrict__ lf,
    const float* __restrict__ key_w, const float* __restrict__ key_b,
    const float* __restrict__ value_w, const float* __restrict__ value_b)
{
    __shared__ __align__(16) float As[16][64];
    __shared__ __align__(16) float Bs[16][64];

    const int tid = threadIdx.x;
    const int m0 = blockIdx.x * 64;
    const int n0 = blockIdx.y * 64;
    const int ty = tid >> 4;
    const int tx = tid & 15;

    float acc[4][4];
#pragma unroll
    for (int i = 0; i < 4; i++)
#pragma unroll
        for (int j = 0; j < 4; j++) acc[i][j] = 0.f;

    const int mi = tid >> 2;
    const int kq = (tid & 3) * 4;

    for (int kb = 0; kb < DD; kb += 16) {
        {
            float4 v = *reinterpret_cast<const float4*>(&lf[(size_t)(m0 + mi) * DD + kb + kq]);
            As[kq + 0][mi] = v.x; As[kq + 1][mi] = v.y; As[kq + 2][mi] = v.z; As[kq + 3][mi] = v.w;
        }
        {
            int n = n0 + mi;
            const float* wrow = (n < CC) ? (key_w + (size_t)n * DD) : (value_w + (size_t)(n - CC) * DD);
            float4 v = *reinterpret_cast<const float4*>(&wrow[kb + kq]);
            Bs[kq + 0][mi] = v.x; Bs[kq + 1][mi] = v.y; Bs[kq + 2][mi] = v.z; Bs[kq + 3][mi] = v.w;
        }
        __syncthreads();
#pragma unroll
        for (int k = 0; k < 16; k++) {
            float4 av = *reinterpret_cast<const float4*>(&As[k][ty * 4]);
            float4 bv = *reinterpret_cast<const float4*>(&Bs[k][tx * 4]);
            float aa[4] = {av.x, av.y, av.z, av.w};
            float bb[4] = {bv.x, bv.y, bv.z, bv.w};
#pragma unroll
            for (int i = 0; i < 4; i++)
#pragma unroll
                for (int j = 0; j < 4; j++) acc[i][j] = fmaf(aa[i], bb[j], acc[i][j]);
        }
        __syncthreads();
    }

#pragma unroll
    for (int i = 0; i < 4; i++) {
        int m = m0 + ty * 4 + i;
        int l = m >> 7, b = m & 127;
#pragma unroll
        for (int j = 0; j < 4; j++) {
            int n = n0 + tx * 4 + j;
            if (n < CC)
                g_keyfT[((size_t)b << 16) + (size_t)n * 512 + l] = acc[i][j] + key_b[n];
            else
                g_valf[((size_t)b << 16) + (size_t)l * CC + (n - CC)] = acc[i][j] + value_b[n - CC];
        }
    }
}

// ---------------- precompute: embW ----------------
__global__ void __launch_bounds__(256) embw_kernel(
    const float* __restrict__ emb, const float* __restrict__ w_ih0,
    const float* __restrict__ b_ih0, const float* __restrict__ b_hh0)
{
    __shared__ float es[EE];
    const int v = blockIdx.x, tid = threadIdx.x;
    for (int i = tid; i < EE; i += 256) es[i] = emb[(size_t)v * EE + i];
    __syncthreads();
    for (int j = tid; j < G4H; j += 256) {
        const float* wr = w_ih0 + (size_t)j * (EE + CC);
        float a0 = b_ih0[j] + b_hh0[j], a1 = 0.f, a2 = 0.f, a3 = 0.f;
        for (int e = 0; e < EE; e += 4) {
            a0 = fmaf(es[e + 0], wr[e + 0], a0);
            a1 = fmaf(es[e + 1], wr[e + 1], a1);
            a2 = fmaf(es[e + 2], wr[e + 2], a2);
            a3 = fmaf(es[e + 3], wr[e + 3], a3);
        }
        g_embW[(size_t)v * G4H + j] = a0 + a1 + a2 + a3;
    }
}

// ---------------- precompute: misc (fused) ----------------
__global__ void __launch_bounds__(256) misc_kernel(
    const float* __restrict__ bi1, const float* __restrict__ bh1,
    const float* __restrict__ bi2, const float* __restrict__ bh2,
    const float* __restrict__ phi_w, const int* __restrict__ transcript,
    const float* __restrict__ hx0, const float* __restrict__ cx0,
    const float* __restrict__ hx1, const float* __restrict__ cx1,
    const float* __restrict__ hx2, const float* __restrict__ cx2)
{
    int i = blockIdx.x * 256 + threadIdx.x;
    if (i == 0) g_barctr = 0;
    if (i < G4H) { g_bias1[i] = bi1[i] + bh1[i]; g_bias2[i] = bi2[i] + bh2[i]; }
    if (i < HH * CC) {
        int k = i >> 7, c = i & 127;
        g_phiT[i] = phi_w[(size_t)c * HH + k];
    }
    if (i < TT * BB) {
        int t = i / BB, b = i % BB;
        g_tok[i] = (t == 0) ? 0 : transcript[(size_t)(t - 1) * BB + b];
    }
    if (i < HH * BB) {
        int k = i >> 7, b = i & 127;
        g_h0T[0][i] = hx0[k]; g_c0T[i] = cx0[k];
        g_h1T[0][i] = hx1[k]; g_c1T[i] = cx1[k];
        g_h2T[0][i] = hx2[k]; g_c2T[i] = cx2[k];
        g_h2n[(size_t)b * HH + k] = hx2[k];
    }
}

// ---------------- launch ----------------
extern "C" void kernel_launch(void* const* d_in, const int* in_sizes, int n_in,
                              void* d_out, int out_size)
{
    const float* lf         = (const float*)d_in[0];
    const int*   lens       = (const int*)  d_in[1];
    const int*   transcript = (const int*)  d_in[2];
    const float* emb        = (const float*)d_in[3];
    const float* w_ih0 = (const float*)d_in[4];
    const float* w_hh0 = (const float*)d_in[5];
    const float* b_ih0 = (const float*)d_in[6];
    const float* b_hh0 = (const float*)d_in[7];
    const float* w_ih1 = (const float*)d_in[8];
    const float* w_hh1 = (const float*)d_in[9];
    const float* b_ih1 = (const float*)d_in[10];
    const float* b_hh1 = (const float*)d_in[11];
    const float* w_ih2 = (const float*)d_in[12];
    const float* w_hh2 = (const float*)d_in[13];
    const float* b_ih2 = (const float*)d_in[14];
    const float* b_hh2 = (const float*)d_in[15];
    const float* phi_w = (const float*)d_in[16];
    const float* phi_b = (const float*)d_in[17];
    const float* key_w = (const float*)d_in[18];
    const float* key_b = (const float*)d_in[19];
    const float* value_w = (const float*)d_in[20];
    const float* value_b = (const float*)d_in[21];
    const float* out_w = (const float*)d_in[22];
    const float* out_b = (const float*)d_in[23];
    const float* hx0 = (const float*)d_in[24];
    const float* cx0 = (const float*)d_in[25];
    const float* hx1 = (const float*)d_in[26];
    const float* cx1 = (const float*)d_in[27];
    const float* hx2 = (const float*)d_in[28];
    const float* cx2 = (const float*)d_in[29];

    float* out = (float*)d_out;
    float* logits_base = out;                        // [T,B,V]
    float* attn_base   = out + (size_t)TT * BB * VV; // [T,B,L]

    keyval_kernel<<<dim3(1024, 4), 256>>>(lf, key_w, key_b, value_w, value_b);
    embw_kernel<<<VV, 256>>>(emb, w_ih0, b_ih0, b_hh0);
    misc_kernel<<<256, 256>>>(b_ih1, b_hh1, b_ih2, b_hh2, phi_w, transcript,
                              hx0, cx0, hx1, cx1, hx2, cx2);
    speller_persistent<<<NBLK, 256>>>(w_ih0, w_hh0, w_ih1, w_hh1, w_ih2, w_hh2,
                                      lens, phi_b, out_w, out_b,
                                      attn_base, logits_base);
}